// round 6
// baseline (speedup 1.0000x reference)
#include <cuda_runtime.h>
#include <math.h>

static constexpr int NG  = 512;
static constexpr int IMW = 256;
static constexpr int IMH = 256;
static constexpr int TW  = 32;   // tile width  (one warp = one pixel row)
static constexpr int TH  = 16;   // tile height (16 warps)
static constexpr int NTX = IMW / TW;   // 8
static constexpr int NTY = IMH / TH;   // 16
static constexpr float TANFOVX = 0.5f;
static constexpr float TANFOVY = 0.5f;
static constexpr float FXc = IMW / (2.0f * TANFOVX);
static constexpr float FYc = IMH / (2.0f * TANFOVY);
static constexpr float TBREAK = 1e-4f;   // warp early-out threshold (abs err << 1e-3 tol)

__global__ void __launch_bounds__(512) fused_raster_kernel(
    const float* __restrict__ means3D,
    const float* __restrict__ opac,
    const float* __restrict__ cols,
    const float* __restrict__ scales,
    const float* __restrict__ rots,
    const float* __restrict__ bg,
    const float* __restrict__ vm_g,
    const float* __restrict__ pm_g,
    float* __restrict__ out)
{
    // tile-compacted, depth-sorted per-gaussian params
    __shared__ float4 s_g0[NG];   // mx, my, -A/2, -B
    __shared__ float4 s_g1[NG];   // -C/2, op, z, cr
    __shared__ float2 s_g2[NG];   // cg, cb
    __shared__ float  s_my[NG];   // my (conflict-free per-lane cull read)
    __shared__ float  s_r2[NG];   // squared reach (1/255 bound)
    __shared__ float  vm[16], pm[16], s_bg[3];
    __shared__ int    s_wsum[16], s_woff[16], s_count;

    const int tid = threadIdx.x;
    if (tid < 16) { vm[tid] = vm_g[tid]; pm[tid] = pm_g[tid]; }
    if (tid < 3)  { s_bg[tid] = bg[tid]; }
    __syncthreads();

    const int tilex = blockIdx.x & (NTX - 1);
    const int tiley = blockIdx.x >> 3;
    const float x0 = (float)(tilex * TW), y0 = (float)(tiley * TH);
    const float x1 = x0 + (TW - 1), y1 = y0 + (TH - 1);

    // ---- fused preprocess (1 gaussian/thread) + tile compaction ----
    const int g = tid;  // NG == blockDim.x

    float m0 = means3D[3*g+0], m1 = means3D[3*g+1], m2 = means3D[3*g+2];

    float4 q4 = ((const float4*)rots)[g];
    float qr = q4.x, qx = q4.y, qy = q4.z, qz = q4.w;
    float qn = rsqrtf(qr*qr + qx*qx + qy*qy + qz*qz);
    qr *= qn; qx *= qn; qy *= qn; qz *= qn;
    float R[3][3] = {
        {1.f - 2.f*(qy*qy + qz*qz), 2.f*(qx*qy - qr*qz),       2.f*(qx*qz + qr*qy)},
        {2.f*(qx*qy + qr*qz),       1.f - 2.f*(qx*qx + qz*qz), 2.f*(qy*qz - qr*qx)},
        {2.f*(qx*qz - qr*qy),       2.f*(qy*qz + qr*qx),       1.f - 2.f*(qx*qx + qy*qy)}};

    float sc0 = scales[3*g+0], sc1 = scales[3*g+1], sc2 = scales[3*g+2];
    float M[3][3];
    #pragma unroll
    for (int r = 0; r < 3; r++) {
        M[r][0] = R[r][0] * sc0;
        M[r][1] = R[r][1] * sc1;
        M[r][2] = R[r][2] * sc2;
    }
    float Sg[3][3];
    #pragma unroll
    for (int a = 0; a < 3; a++)
        #pragma unroll
        for (int b = 0; b < 3; b++)
            Sg[a][b] = M[a][0]*M[b][0] + M[a][1]*M[b][1] + M[a][2]*M[b][2];

    float t0 = m0*vm[0] + m1*vm[4] + m2*vm[8]  + vm[12];
    float t1 = m0*vm[1] + m1*vm[5] + m2*vm[9]  + vm[13];
    float tz = m0*vm[2] + m1*vm[6] + m2*vm[10] + vm[14];
    float tzc = fmaxf(tz, 0.0001f);
    const float limx = 1.3f * TANFOVX, limy = 1.3f * TANFOVY;
    float txc = fminf(fmaxf(t0 / tzc, -limx), limx) * tzc;
    float tyc = fminf(fmaxf(t1 / tzc, -limy), limy) * tzc;

    float J[2][3] = {
        {FXc / tzc, 0.f,       -FXc * txc / (tzc * tzc)},
        {0.f,       FYc / tzc, -FYc * tyc / (tzc * tzc)}};

    float T2[2][3];
    #pragma unroll
    for (int a = 0; a < 2; a++)
        #pragma unroll
        for (int k = 0; k < 3; k++)
            T2[a][k] = J[a][0]*vm[k*4+0] + J[a][1]*vm[k*4+1] + J[a][2]*vm[k*4+2];

    float U[2][3];
    #pragma unroll
    for (int a = 0; a < 2; a++)
        #pragma unroll
        for (int k = 0; k < 3; k++)
            U[a][k] = T2[a][0]*Sg[0][k] + T2[a][1]*Sg[1][k] + T2[a][2]*Sg[2][k];

    float c00 = U[0][0]*T2[0][0] + U[0][1]*T2[0][1] + U[0][2]*T2[0][2] + 0.3f;
    float c01 = U[0][0]*T2[1][0] + U[0][1]*T2[1][1] + U[0][2]*T2[1][2];
    float c11 = U[1][0]*T2[1][0] + U[1][1]*T2[1][1] + U[1][2]*T2[1][2] + 0.3f;

    float det = c00*c11 - c01*c01;
    float det_inv = 1.0f / (det != 0.f ? det : 1.f);
    float Ai = c11 * det_inv;
    float Bi = -c01 * det_inv;
    float Ci = c00 * det_inv;
    float mid = 0.5f * (c00 + c11);
    float lam = mid + sqrtf(fmaxf(mid*mid - det, 0.1f));
    bool vis = (det > 0.f) && (tz > 0.2f);

    if (blockIdx.x == 0)
        out[5 * IMH * IMW + g] = vis ? ceilf(3.0f * sqrtf(lam)) : 0.0f;

    float p0h = m0*pm[0] + m1*pm[4] + m2*pm[8]  + pm[12];
    float p1h = m0*pm[1] + m1*pm[5] + m2*pm[9]  + pm[13];
    float p3h = m0*pm[3] + m1*pm[7] + m2*pm[11] + pm[15];
    float pw = 1.0f / (p3h + 1e-7f);
    float mx = ((p0h*pw + 1.0f) * IMW - 1.0f) * 0.5f;
    float my = ((p1h*pw + 1.0f) * IMH - 1.0f) * 0.5f;

    float op = opac[g];
    float r2 = -1.f;
    if (vis && (op * 255.f > 1.f)) {
        // alpha >= 1/255 requires |d|^2 <= 2*lam*ln(255*op)  (lam >= lambda_max)
        r2 = 2.0f * lam * logf(255.f * op);
    } else {
        op = 0.f;
    }

    // tile overlap test (conservative-exact vs the 1/255 cutoff)
    float cx = fminf(fmaxf(mx, x0), x1);
    float cy = fminf(fmaxf(my, y0), y1);
    float ddx = mx - cx, ddy = my - cy;
    bool keep = (r2 >= 0.f) && (ddx*ddx + ddy*ddy <= r2);

    unsigned bal = __ballot_sync(0xffffffffu, keep);
    const int lane = tid & 31, warp = tid >> 5;
    if (lane == 0) s_wsum[warp] = __popc(bal);
    __syncthreads();
    if (tid == 0) {
        int acc = 0;
        #pragma unroll
        for (int w = 0; w < 16; w++) { s_woff[w] = acc; acc += s_wsum[w]; }
        s_count = acc;
    }
    __syncthreads();
    if (keep) {
        int pos = s_woff[warp] + __popc(bal & ((1u << lane) - 1u));
        s_g0[pos] = make_float4(mx, my, -0.5f * Ai, -Bi);
        s_g1[pos] = make_float4(-0.5f * Ci, op, tz, cols[3*g+0]);
        s_g2[pos] = make_float2(cols[3*g+1], cols[3*g+2]);
        s_my[pos] = my;
        s_r2[pos] = r2;
    }
    __syncthreads();

    // ---- register-staged stable rank sort by depth (in place) ----
    const int count = s_count;
    const bool active = (tid < count);
    float4 r0, r1;
    float2 r2v;
    float rmy = 0.f, rr2 = 0.f;
    int rank = 0;
    if (active) {
        r0  = s_g0[tid];
        r1  = s_g1[tid];
        r2v = s_g2[tid];
        rmy = s_my[tid];
        rr2 = s_r2[tid];
        float zk = r1.z;
        for (int j = 0; j < count; j++) {
            float zj = s_g1[j].z;   // broadcast read
            rank += (zj < zk) || (zj == zk && j < tid);
        }
    }
    __syncthreads();
    if (active) {
        s_g0[rank] = r0; s_g1[rank] = r1; s_g2[rank] = r2v;
        s_my[rank] = rmy; s_r2[rank] = rr2;
    }
    __syncthreads();

    // ---- fused per-row cull + per-pixel compositing (ballot bit-iteration) ----
    const int row = warp;                   // warp w owns pixel row y0 + w
    const float pyr = y0 + (float)row;
    const float px = x0 + (float)lane;

    float T = 1.f, cr = 0.f, cg = 0.f, cb = 0.f, dep = 0.f;
    for (int base = 0; base < count; base += 32) {
        int kc = base + lane;
        bool ok = false;
        if (kc < count) {
            float dyr = s_my[kc] - pyr;     // conflict-free LDS.32
            ok = (dyr * dyr <= s_r2[kc]);   // else alpha < 1/255 for entire row (exact)
        }
        unsigned b = __ballot_sync(0xffffffffu, ok);
        while (b) {                          // warp-uniform, order-preserving
            int k = base + (__ffs(b) - 1);
            b &= b - 1;
            float4 q0 = s_g0[k];             // broadcast LDS.128
            float4 q1 = s_g1[k];
            float2 q2 = s_g2[k];
            float dx = q0.x - px;
            float dy = q0.y - pyr;
            // power = -A/2*dx^2 - B*dx*dy - C/2*dy^2 (constants pre-folded)
            float t  = fmaf(q0.z, dx, q0.w * dy);
            float power = fmaf(t, dx, (q1.x * dy) * dy);
            float a = fminf(0.99f, q1.y * __expf(power));
            a = ((power <= 0.f) && (a >= 1.f / 255.f)) ? a : 0.f;
            float w = a * T;
            cr  += w * q1.w;
            cg  += w * q2.x;
            cb  += w * q2.y;
            dep += w * q1.z;
            T   -= w;                        // T *= (1 - a)
        }
        // warp early-out: remaining contributions bounded by T < TBREAK << tol
        if (__ballot_sync(0xffffffffu, T > TBREAK) == 0u) break;
    }

    const int pidx = (tiley * TH + row) * IMW + tilex * TW + lane;
    const int HW = IMH * IMW;
    out[0*HW + pidx] = cr + T * s_bg[0];
    out[1*HW + pidx] = cg + T * s_bg[1];
    out[2*HW + pidx] = cb + T * s_bg[2];
    out[3*HW + pidx] = dep;   // depth
    out[4*HW + pidx] = T;     // Tfinal
}

extern "C" void kernel_launch(void* const* d_in, const int* in_sizes, int n_in,
                              void* d_out, int out_size)
{
    const float* means3D = (const float*)d_in[0];
    const float* opac    = (const float*)d_in[1];
    const float* cols    = (const float*)d_in[2];
    const float* scales  = (const float*)d_in[3];
    const float* rots    = (const float*)d_in[4];
    const float* bg      = (const float*)d_in[5];
    const float* vm      = (const float*)d_in[6];
    const float* pm      = (const float*)d_in[7];
    float* out = (float*)d_out;

    // output layout: color(3*H*W), depth(H*W), Tfinal(H*W), radii(N)
    fused_raster_kernel<<<NTX * NTY, 512>>>(means3D, opac, cols, scales, rots,
                                            bg, vm, pm, out);
}

// round 8
// speedup vs baseline: 2.7059x; 2.7059x over previous
#include <cuda_runtime.h>
#include <math.h>

static constexpr int NG  = 512;
static constexpr int IMW = 256;
static constexpr int IMH = 256;
static constexpr int TW  = 32;   // tile width  (one warp = one pixel row)
static constexpr int TH  = 16;   // tile height (16 warps)
static constexpr int NTX = IMW / TW;   // 8
static constexpr int NTY = IMH / TH;   // 16
static constexpr float TANFOVX = 0.5f;
static constexpr float TANFOVY = 0.5f;
static constexpr float FXc = IMW / (2.0f * TANFOVX);
static constexpr float FYc = IMH / (2.0f * TANFOVY);

__global__ void __launch_bounds__(512) fused_raster_kernel(
    const float* __restrict__ means3D,
    const float* __restrict__ opac,
    const float* __restrict__ cols,
    const float* __restrict__ scales,
    const float* __restrict__ rots,
    const float* __restrict__ bg,
    const float* __restrict__ vm_g,
    const float* __restrict__ pm_g,
    float* __restrict__ out)
{
    // tile-compacted, depth-sorted per-gaussian params
    __shared__ float4 s_p0[NG];           // mx, my, -A/2, -B
    __shared__ float4 s_p1[NG];           // -C/2, op, z, cr
    __shared__ float2 s_p2[NG];           // cg, cb
    __shared__ float  s_z[NG + 4];        // sort keys (+4 pad slots for x4 unroll)
    __shared__ float  s_my[NG];           // my (conflict-free per-lane cull read)
    __shared__ float  s_r2[NG];           // squared reach (1/255 bound)
    __shared__ unsigned short s_idx[TH][NG];  // per-row culled index lists
    __shared__ float  vm[16], pm[16], s_bg[3];
    __shared__ int    s_wsum[16], s_woff[16], s_count;

    const int tid = threadIdx.x;

    // ---- issue ALL global input loads up front (overlap DRAM latency w/ math) ----
    const int g = tid;  // NG == blockDim.x
    float m0 = means3D[3*g+0], m1 = means3D[3*g+1], m2 = means3D[3*g+2];
    float4 q4 = ((const float4*)rots)[g];
    float sc0 = scales[3*g+0], sc1 = scales[3*g+1], sc2 = scales[3*g+2];
    float op  = opac[g];
    float cR  = cols[3*g+0], cG = cols[3*g+1], cB = cols[3*g+2];

    if (tid < 16) { vm[tid] = vm_g[tid]; pm[tid] = pm_g[tid]; }
    if (tid < 3)  { s_bg[tid] = bg[tid]; }
    __syncthreads();

    const int tilex = blockIdx.x & (NTX - 1);
    const int tiley = blockIdx.x >> 3;
    const float x0 = (float)(tilex * TW), y0 = (float)(tiley * TH);
    const float x1 = x0 + (TW - 1), y1 = y0 + (TH - 1);

    // ---- fused preprocess (1 gaussian/thread) ----
    float qr = q4.x, qx = q4.y, qy = q4.z, qz = q4.w;
    float qn = rsqrtf(qr*qr + qx*qx + qy*qy + qz*qz);
    qr *= qn; qx *= qn; qy *= qn; qz *= qn;
    float R[3][3] = {
        {1.f - 2.f*(qy*qy + qz*qz), 2.f*(qx*qy - qr*qz),       2.f*(qx*qz + qr*qy)},
        {2.f*(qx*qy + qr*qz),       1.f - 2.f*(qx*qx + qz*qz), 2.f*(qy*qz - qr*qx)},
        {2.f*(qx*qz - qr*qy),       2.f*(qy*qz + qr*qx),       1.f - 2.f*(qx*qx + qy*qy)}};

    float M[3][3];
    #pragma unroll
    for (int r = 0; r < 3; r++) {
        M[r][0] = R[r][0] * sc0;
        M[r][1] = R[r][1] * sc1;
        M[r][2] = R[r][2] * sc2;
    }
    float Sg[3][3];
    #pragma unroll
    for (int a = 0; a < 3; a++)
        #pragma unroll
        for (int b = 0; b < 3; b++)
            Sg[a][b] = M[a][0]*M[b][0] + M[a][1]*M[b][1] + M[a][2]*M[b][2];

    float t0 = m0*vm[0] + m1*vm[4] + m2*vm[8]  + vm[12];
    float t1 = m0*vm[1] + m1*vm[5] + m2*vm[9]  + vm[13];
    float tz = m0*vm[2] + m1*vm[6] + m2*vm[10] + vm[14];
    float tzc = fmaxf(tz, 0.0001f);
    const float limx = 1.3f * TANFOVX, limy = 1.3f * TANFOVY;
    float txc = fminf(fmaxf(t0 / tzc, -limx), limx) * tzc;
    float tyc = fminf(fmaxf(t1 / tzc, -limy), limy) * tzc;

    float J[2][3] = {
        {FXc / tzc, 0.f,       -FXc * txc / (tzc * tzc)},
        {0.f,       FYc / tzc, -FYc * tyc / (tzc * tzc)}};

    float T2[2][3];
    #pragma unroll
    for (int a = 0; a < 2; a++)
        #pragma unroll
        for (int k = 0; k < 3; k++)
            T2[a][k] = J[a][0]*vm[k*4+0] + J[a][1]*vm[k*4+1] + J[a][2]*vm[k*4+2];

    float U[2][3];
    #pragma unroll
    for (int a = 0; a < 2; a++)
        #pragma unroll
        for (int k = 0; k < 3; k++)
            U[a][k] = T2[a][0]*Sg[0][k] + T2[a][1]*Sg[1][k] + T2[a][2]*Sg[2][k];

    float c00 = U[0][0]*T2[0][0] + U[0][1]*T2[0][1] + U[0][2]*T2[0][2] + 0.3f;
    float c01 = U[0][0]*T2[1][0] + U[0][1]*T2[1][1] + U[0][2]*T2[1][2];
    float c11 = U[1][0]*T2[1][0] + U[1][1]*T2[1][1] + U[1][2]*T2[1][2] + 0.3f;

    float det = c00*c11 - c01*c01;
    float det_inv = 1.0f / (det != 0.f ? det : 1.f);
    float Ai = c11 * det_inv;
    float Bi = -c01 * det_inv;
    float Ci = c00 * det_inv;
    float mid = 0.5f * (c00 + c11);
    float lam = mid + sqrtf(fmaxf(mid*mid - det, 0.1f));
    bool vis = (det > 0.f) && (tz > 0.2f);

    if (blockIdx.x == 0)
        out[5 * IMH * IMW + g] = vis ? ceilf(3.0f * sqrtf(lam)) : 0.0f;

    float p0h = m0*pm[0] + m1*pm[4] + m2*pm[8]  + pm[12];
    float p1h = m0*pm[1] + m1*pm[5] + m2*pm[9]  + pm[13];
    float p3h = m0*pm[3] + m1*pm[7] + m2*pm[11] + pm[15];
    float pw = 1.0f / (p3h + 1e-7f);
    float mx = ((p0h*pw + 1.0f) * IMW - 1.0f) * 0.5f;
    float my = ((p1h*pw + 1.0f) * IMH - 1.0f) * 0.5f;

    float r2 = -1.f;
    if (vis && (op * 255.f > 1.f)) {
        // alpha >= 1/255 requires |d|^2 <= 2*lam*ln(255*op)  (lam >= lambda_max)
        r2 = 2.0f * lam * logf(255.f * op);
    } else {
        op = 0.f;
    }

    // tile overlap test (conservative-exact vs the 1/255 cutoff)
    float cx = fminf(fmaxf(mx, x0), x1);
    float cy = fminf(fmaxf(my, y0), y1);
    float ddx = mx - cx, ddy = my - cy;
    bool keep = (r2 >= 0.f) && (ddx*ddx + ddy*ddy <= r2);

    unsigned bal = __ballot_sync(0xffffffffu, keep);
    const int lane = tid & 31, warp = tid >> 5;
    if (lane == 0) s_wsum[warp] = __popc(bal);
    __syncthreads();
    if (tid == 0) {
        int acc = 0;
        #pragma unroll
        for (int w = 0; w < 16; w++) { s_woff[w] = acc; acc += s_wsum[w]; }
        s_count = acc;
    }
    __syncthreads();
    if (keep) {
        int pos = s_woff[warp] + __popc(bal & ((1u << lane) - 1u));
        s_p0[pos] = make_float4(mx, my, -0.5f * Ai, -Bi);
        s_p1[pos] = make_float4(-0.5f * Ci, op, tz, cR);
        s_p2[pos] = make_float2(cG, cB);
        s_z[pos]  = tz;
        s_my[pos] = my;
        s_r2[pos] = r2;
    }
    // FIX (R7 bug): pad the 4 slots just past the compacted list so the
    // x4-unrolled scan below never reads uninitialized shared memory.
    if (tid < 4) s_z[s_count + tid] = 1e30f;
    __syncthreads();

    // ---- register-staged stable rank sort by depth (x4-unrolled scan) ----
    const int count = s_count;
    const bool active = (tid < count);
    float4 r0, r1;
    float2 r2v;
    float rmy = 0.f, rr2 = 0.f;
    int rank = 0;
    if (active) {
        r0  = s_p0[tid];
        r1  = s_p1[tid];
        r2v = s_p2[tid];
        rmy = s_my[tid];
        rr2 = s_r2[tid];
        float zk = r1.z;
        // 4 independent LDS per iter; pad keys are 1e30 (> any real depth,
        // never equal), so over-read indices contribute 0 to rank.
        for (int j = 0; j < count; j += 4) {
            float z0v = s_z[j+0], z1v = s_z[j+1], z2v = s_z[j+2], z3v = s_z[j+3];
            rank += (z0v < zk) || (z0v == zk && (j+0) < tid);
            rank += (z1v < zk) || (z1v == zk && (j+1) < tid);
            rank += (z2v < zk) || (z2v == zk && (j+2) < tid);
            rank += (z3v < zk) || (z3v == zk && (j+3) < tid);
        }
    }
    __syncthreads();
    if (active) {
        s_p0[rank] = r0; s_p1[rank] = r1; s_p2[rank] = r2v;
        s_my[rank] = rmy; s_r2[rank] = rr2;
    }
    __syncthreads();

    // ---- per-warp (per-row) culling: drop gaussians that provably miss the row ----
    const int row = warp;                   // warp w owns pixel row y0 + w
    const float pyr = y0 + (float)row;
    int wcount = 0;
    for (int base = 0; base < count; base += 32) {
        int k = base + lane;
        bool ok = false;
        if (k < count) {
            float dyr = s_my[k] - pyr;
            ok = (dyr * dyr <= s_r2[k]);    // else alpha < 1/255 for entire row (exact)
        }
        unsigned b = __ballot_sync(0xffffffffu, ok);
        if (ok)
            s_idx[row][wcount + __popc(b & ((1u << lane) - 1u))] = (unsigned short)k;
        wcount += __popc(b);
    }

    // ---- per-pixel front-to-back compositing (branchless) ----
    const float px = x0 + (float)lane;

    float T = 1.f, cr = 0.f, cg = 0.f, cb = 0.f, dep = 0.f;
    #pragma unroll 4
    for (int i = 0; i < wcount; i++) {
        int k = (int)s_idx[row][i];         // warp-uniform broadcast
        float4 q0 = s_p0[k];
        float4 q1 = s_p1[k];
        float2 q2 = s_p2[k];
        float dx = q0.x - px;
        float dy = q0.y - pyr;
        // power = -A/2*dx^2 - B*dx*dy - C/2*dy^2 (constants pre-folded)
        float t  = fmaf(q0.z, dx, q0.w * dy);
        float power = fmaf(t, dx, (q1.x * dy) * dy);
        float a = fminf(0.99f, q1.y * __expf(power));
        a = ((power <= 0.f) && (a >= 1.f / 255.f)) ? a : 0.f;
        float w = a * T;
        cr  += w * q1.w;
        cg  += w * q2.x;
        cb  += w * q2.y;
        dep += w * q1.z;
        T   -= w;                            // T *= (1 - a)
    }

    const int pidx = (tiley * TH + row) * IMW + tilex * TW + lane;
    const int HW = IMH * IMW;
    out[0*HW + pidx] = cr + T * s_bg[0];
    out[1*HW + pidx] = cg + T * s_bg[1];
    out[2*HW + pidx] = cb + T * s_bg[2];
    out[3*HW + pidx] = dep;   // depth
    out[4*HW + pidx] = T;     // Tfinal
}

extern "C" void kernel_launch(void* const* d_in, const int* in_sizes, int n_in,
                              void* d_out, int out_size)
{
    const float* means3D = (const float*)d_in[0];
    const float* opac    = (const float*)d_in[1];
    const float* cols    = (const float*)d_in[2];
    const float* scales  = (const float*)d_in[3];
    const float* rots    = (const float*)d_in[4];
    const float* bg      = (const float*)d_in[5];
    const float* vm      = (const float*)d_in[6];
    const float* pm      = (const float*)d_in[7];
    float* out = (float*)d_out;

    // output layout: color(3*H*W), depth(H*W), Tfinal(H*W), radii(N)
    fused_raster_kernel<<<NTX * NTY, 512>>>(means3D, opac, cols, scales, rots,
                                            bg, vm, pm, out);
}